// round 1
// baseline (speedup 1.0000x reference)
#include <cuda_runtime.h>
#include <math.h>

// Problem constants: b=2, s=2048, d=2048, H=16, Dh=128, window=2048 (never binds -> causal)
#define GM 4096   // b*s
#define GD 2048   // model dim
#define SEQ 2048
#define NH 16
#define DH 128

// Scratch (device globals: allocation is forbidden, statics are allowed)
__device__ float g_Q[GM * GD];
__device__ float g_K[GM * GD];
__device__ float g_V[GM * GD];
__device__ float g_C[GM * GD];

// ---------------------------------------------------------------------------
// SGEMM: C[M,N] = A[M,K] @ B[K,N], all row-major, fp32.
// 128x128 tile, KT=16, 256 threads, 8x8 register blocking per thread.
// ---------------------------------------------------------------------------
__global__ __launch_bounds__(256, 1) void sgemm_kernel(
    const float* __restrict__ A, const float* __restrict__ B,
    float* __restrict__ C, int M, int N, int K)
{
    __shared__ float As[16][132];  // transposed: As[k][m]
    __shared__ float Bs[16][132];  // Bs[k][n]

    const int tid = threadIdx.x;
    const int tx = tid & 15;       // n-direction
    const int ty = tid >> 4;       // m-direction
    const int m0 = blockIdx.y * 128;
    const int n0 = blockIdx.x * 128;

    float acc[8][8];
#pragma unroll
    for (int i = 0; i < 8; i++)
#pragma unroll
        for (int j = 0; j < 8; j++) acc[i][j] = 0.0f;

    for (int k0 = 0; k0 < K; k0 += 16) {
        // A tile: 128 rows x 16 k, store transposed As[k][m]
#pragma unroll
        for (int i = 0; i < 8; i++) {
            int idx = tid + i * 256;      // 0..2047
            int m = idx >> 4;
            int kk = idx & 15;
            As[kk][m] = A[(size_t)(m0 + m) * K + k0 + kk];
        }
        // B tile: 16 k x 128 n, vectorized
#pragma unroll
        for (int i = 0; i < 2; i++) {
            int idx = tid + i * 256;      // 0..511 float4 units
            int kk = idx >> 5;
            int n4 = (idx & 31) << 2;
            float4 v = *reinterpret_cast<const float4*>(&B[(size_t)(k0 + kk) * N + n0 + n4]);
            Bs[kk][n4 + 0] = v.x; Bs[kk][n4 + 1] = v.y;
            Bs[kk][n4 + 2] = v.z; Bs[kk][n4 + 3] = v.w;
        }
        __syncthreads();

#pragma unroll
        for (int kk = 0; kk < 16; kk++) {
            float4 a0 = *reinterpret_cast<const float4*>(&As[kk][ty * 8]);
            float4 a1 = *reinterpret_cast<const float4*>(&As[kk][ty * 8 + 4]);
            float4 b0 = *reinterpret_cast<const float4*>(&Bs[kk][tx * 8]);
            float4 b1 = *reinterpret_cast<const float4*>(&Bs[kk][tx * 8 + 4]);
            float a[8] = {a0.x, a0.y, a0.z, a0.w, a1.x, a1.y, a1.z, a1.w};
            float b[8] = {b0.x, b0.y, b0.z, b0.w, b1.x, b1.y, b1.z, b1.w};
#pragma unroll
            for (int i = 0; i < 8; i++)
#pragma unroll
                for (int j = 0; j < 8; j++)
                    acc[i][j] = fmaf(a[i], b[j], acc[i][j]);
        }
        __syncthreads();
    }

#pragma unroll
    for (int i = 0; i < 8; i++) {
        float* crow = &C[(size_t)(m0 + ty * 8 + i) * N + n0 + tx * 8];
        float4 c0 = make_float4(acc[i][0], acc[i][1], acc[i][2], acc[i][3]);
        float4 c1 = make_float4(acc[i][4], acc[i][5], acc[i][6], acc[i][7]);
        *reinterpret_cast<float4*>(crow) = c0;
        *reinterpret_cast<float4*>(crow + 4) = c1;
    }
}

// ---------------------------------------------------------------------------
// Causal flash attention (window never binds): per block one (batch, head,
// q-tile of 128). BQ=BK=128, Dh=128. Online softmax, fp32.
// Shared: Qs [d][q] (transposed), Ks [d][k] (transposed, aliased as Ps[k][q]),
//         Vs [k][d].  Stride 132 floats, ~203 KB dynamic smem.
// ---------------------------------------------------------------------------
#define FA_STRIDE 132
#define FA_SMEM_BYTES (3 * 128 * FA_STRIDE * 4)
#define SM_SCALE 0.08838834764831845f  // 1/sqrt(128)

__global__ __launch_bounds__(256, 1) void flash_kernel(
    const float* __restrict__ Qg, const float* __restrict__ Kg,
    const float* __restrict__ Vg, float* __restrict__ Og)
{
    extern __shared__ float sm[];
    float* Qs = sm;                        // [128][132], Qs[d*132+q]
    float* Ks = sm + 128 * FA_STRIDE;      // [128][132], Ks[d*132+k]; later Ps[k*132+q]
    float* Vs = sm + 2 * 128 * FA_STRIDE;  // [128][132], Vs[k*132+d]

    const int tid = threadIdx.x;
    const int tx = tid & 15;   // k-cols / d-cols
    const int ty = tid >> 4;   // q-rows
    const int qt = blockIdx.x;
    const int h  = blockIdx.y;
    const int b  = blockIdx.z;
    const int q0 = qt * 128;
    const size_t base = ((size_t)b * SEQ) * GD + (size_t)h * DH;

    // Load Q tile transposed: Qs[d][q]
#pragma unroll
    for (int i = 0; i < 16; i++) {
        int idx = tid + i * 256;     // 0..4095 float4 units
        int r  = idx >> 5;           // q row 0..127
        int d4 = (idx & 31) << 2;    // d 0..124
        float4 v = *reinterpret_cast<const float4*>(&Qg[base + (size_t)(q0 + r) * GD + d4]);
        Qs[(d4 + 0) * FA_STRIDE + r] = v.x;
        Qs[(d4 + 1) * FA_STRIDE + r] = v.y;
        Qs[(d4 + 2) * FA_STRIDE + r] = v.z;
        Qs[(d4 + 3) * FA_STRIDE + r] = v.w;
    }

    float m_i[8], l_i[8], o[8][8];
#pragma unroll
    for (int i = 0; i < 8; i++) {
        m_i[i] = -1e30f; l_i[i] = 0.0f;
#pragma unroll
        for (int j = 0; j < 8; j++) o[i][j] = 0.0f;
    }

    for (int jt = 0; jt <= qt; jt++) {
        const int k0 = jt * 128;
        __syncthreads();   // previous iter done with Ks(Ps)/Vs; Q load covered too
        // Load K (transposed) and V (natural)
#pragma unroll
        for (int i = 0; i < 16; i++) {
            int idx = tid + i * 256;
            int r  = idx >> 5;
            int d4 = (idx & 31) << 2;
            float4 kv = *reinterpret_cast<const float4*>(&Kg[base + (size_t)(k0 + r) * GD + d4]);
            Ks[(d4 + 0) * FA_STRIDE + r] = kv.x;
            Ks[(d4 + 1) * FA_STRIDE + r] = kv.y;
            Ks[(d4 + 2) * FA_STRIDE + r] = kv.z;
            Ks[(d4 + 3) * FA_STRIDE + r] = kv.w;
            float4 vv = *reinterpret_cast<const float4*>(&Vg[base + (size_t)(k0 + r) * GD + d4]);
            *reinterpret_cast<float4*>(&Vs[r * FA_STRIDE + d4]) = vv;
        }
        __syncthreads();

        // S = Q @ K^T  (8x8 per thread; rows=q=ty*8+i, cols=k=tx*8+j)
        float s[8][8];
#pragma unroll
        for (int i = 0; i < 8; i++)
#pragma unroll
            for (int j = 0; j < 8; j++) s[i][j] = 0.0f;

        for (int d = 0; d < 128; d++) {
            float4 a0 = *reinterpret_cast<const float4*>(&Qs[d * FA_STRIDE + ty * 8]);
            float4 a1 = *reinterpret_cast<const float4*>(&Qs[d * FA_STRIDE + ty * 8 + 4]);
            float4 b0 = *reinterpret_cast<const float4*>(&Ks[d * FA_STRIDE + tx * 8]);
            float4 b1 = *reinterpret_cast<const float4*>(&Ks[d * FA_STRIDE + tx * 8 + 4]);
            float a[8] = {a0.x, a0.y, a0.z, a0.w, a1.x, a1.y, a1.z, a1.w};
            float bb[8] = {b0.x, b0.y, b0.z, b0.w, b1.x, b1.y, b1.z, b1.w};
#pragma unroll
            for (int i = 0; i < 8; i++)
#pragma unroll
                for (int j = 0; j < 8; j++)
                    s[i][j] = fmaf(a[i], bb[j], s[i][j]);
        }

        // scale + causal mask (mask only on the diagonal tile)
        if (jt == qt) {
#pragma unroll
            for (int i = 0; i < 8; i++) {
                int qq = q0 + ty * 8 + i;
#pragma unroll
                for (int j = 0; j < 8; j++) {
                    int kk = k0 + tx * 8 + j;
                    s[i][j] = (kk > qq) ? -1e30f : s[i][j] * SM_SCALE;
                }
            }
        } else {
#pragma unroll
            for (int i = 0; i < 8; i++)
#pragma unroll
                for (int j = 0; j < 8; j++) s[i][j] *= SM_SCALE;
        }

        // Online softmax update (row reduction across 16 lanes of the half-warp)
#pragma unroll
        for (int i = 0; i < 8; i++) {
            float mloc = s[i][0];
#pragma unroll
            for (int j = 1; j < 8; j++) mloc = fmaxf(mloc, s[i][j]);
#pragma unroll
            for (int off = 8; off >= 1; off >>= 1)
                mloc = fmaxf(mloc, __shfl_xor_sync(0xffffffffu, mloc, off, 16));
            float mnew = fmaxf(m_i[i], mloc);
            float corr = __expf(m_i[i] - mnew);
            m_i[i] = mnew;
            float rs = 0.0f;
#pragma unroll
            for (int j = 0; j < 8; j++) {
                float p = __expf(s[i][j] - mnew);
                s[i][j] = p;
                rs += p;
            }
#pragma unroll
            for (int off = 8; off >= 1; off >>= 1)
                rs += __shfl_xor_sync(0xffffffffu, rs, off, 16);
            l_i[i] = l_i[i] * corr + rs;
#pragma unroll
            for (int j = 0; j < 8; j++) o[i][j] *= corr;
        }

        __syncthreads();  // everyone done reading Ks before overwriting with Ps
        // Write P transposed into Ks region: Ps[k][q]
#pragma unroll
        for (int j = 0; j < 8; j++)
#pragma unroll
            for (int i = 0; i < 8; i++)
                Ks[(tx * 8 + j) * FA_STRIDE + ty * 8 + i] = s[i][j];
        __syncthreads();

        // O += P @ V   (rows=q=ty*8+i, cols=d=tx*8+j)
        for (int k = 0; k < 128; k++) {
            float4 a0 = *reinterpret_cast<const float4*>(&Ks[k * FA_STRIDE + ty * 8]);
            float4 a1 = *reinterpret_cast<const float4*>(&Ks[k * FA_STRIDE + ty * 8 + 4]);
            float4 b0 = *reinterpret_cast<const float4*>(&Vs[k * FA_STRIDE + tx * 8]);
            float4 b1 = *reinterpret_cast<const float4*>(&Vs[k * FA_STRIDE + tx * 8 + 4]);
            float a[8] = {a0.x, a0.y, a0.z, a0.w, a1.x, a1.y, a1.z, a1.w};
            float bb[8] = {b0.x, b0.y, b0.z, b0.w, b1.x, b1.y, b1.z, b1.w};
#pragma unroll
            for (int i = 0; i < 8; i++)
#pragma unroll
                for (int j = 0; j < 8; j++)
                    o[i][j] = fmaf(a[i], bb[j], o[i][j]);
        }
    }

    // Epilogue: normalize and store
#pragma unroll
    for (int i = 0; i < 8; i++) {
        float inv = 1.0f / l_i[i];
        float* orow = &Og[base + (size_t)(q0 + ty * 8 + i) * GD + tx * 8];
        float4 c0 = make_float4(o[i][0] * inv, o[i][1] * inv, o[i][2] * inv, o[i][3] * inv);
        float4 c1 = make_float4(o[i][4] * inv, o[i][5] * inv, o[i][6] * inv, o[i][7] * inv);
        *reinterpret_cast<float4*>(orow) = c0;
        *reinterpret_cast<float4*>(orow + 4) = c1;
    }
}

// ---------------------------------------------------------------------------
extern "C" void kernel_launch(void* const* d_in, const int* in_sizes, int n_in,
                              void* d_out, int out_size)
{
    const float* x  = (const float*)d_in[0];
    const float* Wq = (const float*)d_in[1];
    const float* Wk = (const float*)d_in[2];
    const float* Wv = (const float*)d_in[3];
    const float* Wo = (const float*)d_in[4];

    float *Q, *K, *V, *C;
    cudaGetSymbolAddress((void**)&Q, g_Q);
    cudaGetSymbolAddress((void**)&K, g_K);
    cudaGetSymbolAddress((void**)&V, g_V);
    cudaGetSymbolAddress((void**)&C, g_C);

    cudaFuncSetAttribute(flash_kernel,
                         cudaFuncAttributeMaxDynamicSharedMemorySize, FA_SMEM_BYTES);

    dim3 gemm_grid(GD / 128, GM / 128);  // (16, 32)

    sgemm_kernel<<<gemm_grid, 256>>>(x, Wq, Q, GM, GD, GD);
    sgemm_kernel<<<gemm_grid, 256>>>(x, Wk, K, GM, GD, GD);
    sgemm_kernel<<<gemm_grid, 256>>>(x, Wv, V, GM, GD, GD);

    flash_kernel<<<dim3(SEQ / 128, NH, 2), 256, FA_SMEM_BYTES>>>(Q, K, V, C);

    sgemm_kernel<<<gemm_grid, 256>>>(C, Wo, (float*)d_out, GM, GD, GD);
}